// round 1
// baseline (speedup 1.0000x reference)
#include <cuda_runtime.h>

#define EMBED 768
#define HEAD 64
#define SEQ 4096
#define BATCH 4

// Scratch for Q, K, V projections: [B*T, 64] each (4 MB each, fp32)
__device__ float g_Q[BATCH * SEQ * HEAD];
__device__ float g_K[BATCH * SEQ * HEAD];
__device__ float g_V[BATCH * SEQ * HEAD];

// ---------------------------------------------------------------------------
// QKV projection: out[row, h] = x[row, :] @ W[:, h] + b[h]
// grid (256 row-tiles, 3 matrices), 256 threads, 64x64 output tile per block,
// 4x4 register blocking per thread.
// ---------------------------------------------------------------------------
__global__ __launch_bounds__(256) void qkv_kernel(
    const float* __restrict__ x,
    const float* __restrict__ Wq, const float* __restrict__ bq,
    const float* __restrict__ Wk, const float* __restrict__ bk,
    const float* __restrict__ Wv, const float* __restrict__ bv)
{
    __shared__ float sx[64][68];   // [row][e]  (pad 68 -> tr-strided reads hit distinct banks)
    __shared__ float sw[64][68];   // [e][h]

    const float* __restrict__ W;
    const float* __restrict__ bias;
    float* out;
    if (blockIdx.y == 0)      { W = Wq; bias = bq; out = g_Q; }
    else if (blockIdx.y == 1) { W = Wk; bias = bk; out = g_K; }
    else                      { W = Wv; bias = bv; out = g_V; }

    const int t  = threadIdx.x;
    const int tr = t >> 4;    // 0..15 -> rows 4*tr..4*tr+3
    const int tc = t & 15;    // 0..15 -> cols 4*tc..4*tc+3
    const int row0 = blockIdx.x * 64;

    float acc[4][4];
#pragma unroll
    for (int i = 0; i < 4; i++)
#pragma unroll
        for (int j = 0; j < 4; j++) acc[i][j] = 0.f;

    for (int e0 = 0; e0 < EMBED; e0 += 64) {
#pragma unroll
        for (int i = 0; i < 4; i++) {
            int fi = t + i * 256;        // float4 index 0..1023
            int r  = fi >> 4;
            int c  = (fi & 15) << 2;
            *(float4*)&sx[r][c] = *(const float4*)&x[(size_t)(row0 + r) * EMBED + e0 + c];
            *(float4*)&sw[r][c] = *(const float4*)&W[(size_t)(e0 + r) * HEAD + c];
        }
        __syncthreads();

#pragma unroll 8
        for (int e = 0; e < 64; e++) {
            float4 w4 = *(const float4*)&sw[e][tc << 2];
            float q0 = sx[4 * tr + 0][e];
            float q1 = sx[4 * tr + 1][e];
            float q2 = sx[4 * tr + 2][e];
            float q3 = sx[4 * tr + 3][e];
            acc[0][0] += q0 * w4.x; acc[0][1] += q0 * w4.y; acc[0][2] += q0 * w4.z; acc[0][3] += q0 * w4.w;
            acc[1][0] += q1 * w4.x; acc[1][1] += q1 * w4.y; acc[1][2] += q1 * w4.z; acc[1][3] += q1 * w4.w;
            acc[2][0] += q2 * w4.x; acc[2][1] += q2 * w4.y; acc[2][2] += q2 * w4.z; acc[2][3] += q2 * w4.w;
            acc[3][0] += q3 * w4.x; acc[3][1] += q3 * w4.y; acc[3][2] += q3 * w4.z; acc[3][3] += q3 * w4.w;
        }
        __syncthreads();
    }

    float4 b4 = *(const float4*)&bias[tc << 2];
#pragma unroll
    for (int i = 0; i < 4; i++) {
        float4 o;
        o.x = acc[i][0] + b4.x;
        o.y = acc[i][1] + b4.y;
        o.z = acc[i][2] + b4.z;
        o.w = acc[i][3] + b4.w;
        *(float4*)&out[(size_t)(row0 + 4 * tr + i) * HEAD + (tc << 2)] = o;
    }
}

// ---------------------------------------------------------------------------
// Flash attention, causal. BM=BN=64, 256 threads, 4x4 register tile/thread.
// Thread layout: t = tr*16 + tc; the 16 threads of a row group are a half-warp
// so row max/sum reductions use shfl_xor(1,2,4,8).
// sKP buffer is K during S-compute, then reused for P during PV.
// ---------------------------------------------------------------------------
__global__ __launch_bounds__(256) void flash_kernel(float* __restrict__ out)
{
    extern __shared__ float smem[];
    float (*sQ)[68]  = (float (*)[68])smem;                 // 64x68
    float (*sKP)[68] = (float (*)[68])(smem + 64 * 68);     // 64x68 (K, then P)
    float (*sV)[64]  = (float (*)[64])(smem + 2 * 64 * 68); // 64x64

    const int b  = blockIdx.y;
    const int qt = (int)gridDim.x - 1 - (int)blockIdx.x;    // heavy tiles first
    const int t  = threadIdx.x;
    const int tr = t >> 4;
    const int tc = t & 15;

    const float* __restrict__ Q = g_Q + (size_t)b * SEQ * HEAD;
    const float* __restrict__ K = g_K + (size_t)b * SEQ * HEAD;
    const float* __restrict__ V = g_V + (size_t)b * SEQ * HEAD;

    // Load Q tile once
#pragma unroll
    for (int i = 0; i < 4; i++) {
        int fi = t + i * 256;
        int r  = fi >> 4;
        int c  = (fi & 15) << 2;
        *(float4*)&sQ[r][c] = *(const float4*)&Q[(size_t)(qt * 64 + r) * HEAD + c];
    }

    float m[4], l[4], o[4][4];
#pragma unroll
    for (int i = 0; i < 4; i++) {
        m[i] = -1e30f;
        l[i] = 0.f;
#pragma unroll
        for (int j = 0; j < 4; j++) o[i][j] = 0.f;
    }

    for (int kt = 0; kt <= qt; kt++) {
        __syncthreads();   // prior PV reads done (and Q-load visible on first iter)

        // Load K (into sKP) and V tiles
#pragma unroll
        for (int i = 0; i < 4; i++) {
            int fi = t + i * 256;
            int r  = fi >> 4;
            int c  = (fi & 15) << 2;
            *(float4*)&sKP[r][c] = *(const float4*)&K[(size_t)(kt * 64 + r) * HEAD + c];
            *(float4*)&sV[r][c]  = *(const float4*)&V[(size_t)(kt * 64 + r) * HEAD + c];
        }
        __syncthreads();

        // S = Q K^T
        float s[4][4];
#pragma unroll
        for (int i = 0; i < 4; i++)
#pragma unroll
            for (int j = 0; j < 4; j++) s[i][j] = 0.f;

#pragma unroll 8
        for (int h = 0; h < 64; h += 4) {
            float4 q4[4], k4[4];
#pragma unroll
            for (int i = 0; i < 4; i++) q4[i] = *(const float4*)&sQ[4 * tr + i][h];
#pragma unroll
            for (int j = 0; j < 4; j++) k4[j] = *(const float4*)&sKP[4 * tc + j][h];
#pragma unroll
            for (int i = 0; i < 4; i++) {
#pragma unroll
                for (int j = 0; j < 4; j++) {
                    s[i][j] += q4[i].x * k4[j].x + q4[i].y * k4[j].y
                             + q4[i].z * k4[j].z + q4[i].w * k4[j].w;
                }
            }
        }

        // Scale + causal mask (only diag tile needs the mask)
        const float scale = 0.125f;   // 1/sqrt(64)
        if (kt == qt) {
#pragma unroll
            for (int i = 0; i < 4; i++) {
                int qr = 4 * tr + i;
#pragma unroll
                for (int j = 0; j < 4; j++) {
                    int kc = 4 * tc + j;
                    s[i][j] = (kc <= qr) ? s[i][j] * scale : -1e30f;
                }
            }
        } else {
#pragma unroll
            for (int i = 0; i < 4; i++)
#pragma unroll
                for (int j = 0; j < 4; j++) s[i][j] *= scale;
        }

        // Online softmax update (per-row, reduced across the 16-thread row group)
#pragma unroll
        for (int i = 0; i < 4; i++) {
            float mx = fmaxf(fmaxf(s[i][0], s[i][1]), fmaxf(s[i][2], s[i][3]));
            mx = fmaxf(mx, __shfl_xor_sync(0xffffffffu, mx, 1));
            mx = fmaxf(mx, __shfl_xor_sync(0xffffffffu, mx, 2));
            mx = fmaxf(mx, __shfl_xor_sync(0xffffffffu, mx, 4));
            mx = fmaxf(mx, __shfl_xor_sync(0xffffffffu, mx, 8));
            float mn = fmaxf(m[i], mx);
            float alpha = __expf(m[i] - mn);
            m[i] = mn;
            float rs = 0.f;
#pragma unroll
            for (int j = 0; j < 4; j++) {
                s[i][j] = __expf(s[i][j] - mn);
                rs += s[i][j];
            }
            rs += __shfl_xor_sync(0xffffffffu, rs, 1);
            rs += __shfl_xor_sync(0xffffffffu, rs, 2);
            rs += __shfl_xor_sync(0xffffffffu, rs, 4);
            rs += __shfl_xor_sync(0xffffffffu, rs, 8);
            l[i] = l[i] * alpha + rs;
#pragma unroll
            for (int j = 0; j < 4; j++) o[i][j] *= alpha;
        }

        __syncthreads();   // everyone done reading K before P overwrites it

        // Write P tile into the K buffer
#pragma unroll
        for (int i = 0; i < 4; i++) {
            float4 p;
            p.x = s[i][0]; p.y = s[i][1]; p.z = s[i][2]; p.w = s[i][3];
            *(float4*)&sKP[4 * tr + i][tc << 2] = p;
        }
        __syncthreads();

        // O += P @ V
#pragma unroll 8
        for (int k0 = 0; k0 < 64; k0 += 4) {
            float4 p4[4], v4[4];
#pragma unroll
            for (int i = 0; i < 4; i++) p4[i] = *(const float4*)&sKP[4 * tr + i][k0];
#pragma unroll
            for (int kk = 0; kk < 4; kk++) v4[kk] = *(const float4*)&sV[k0 + kk][tc << 2];
#pragma unroll
            for (int i = 0; i < 4; i++) {
                o[i][0] += p4[i].x * v4[0].x + p4[i].y * v4[1].x + p4[i].z * v4[2].x + p4[i].w * v4[3].x;
                o[i][1] += p4[i].x * v4[0].y + p4[i].y * v4[1].y + p4[i].z * v4[2].y + p4[i].w * v4[3].y;
                o[i][2] += p4[i].x * v4[0].z + p4[i].y * v4[1].z + p4[i].z * v4[2].z + p4[i].w * v4[3].z;
                o[i][3] += p4[i].x * v4[0].w + p4[i].y * v4[1].w + p4[i].z * v4[2].w + p4[i].w * v4[3].w;
            }
        }
    }

    // Normalize and write out: [B, T, H]
#pragma unroll
    for (int i = 0; i < 4; i++) {
        float inv = 1.f / l[i];
        float4 r;
        r.x = o[i][0] * inv;
        r.y = o[i][1] * inv;
        r.z = o[i][2] * inv;
        r.w = o[i][3] * inv;
        *(float4*)&out[((size_t)b * SEQ + qt * 64 + 4 * tr + i) * HEAD + (tc << 2)] = r;
    }
}

extern "C" void kernel_launch(void* const* d_in, const int* in_sizes, int n_in,
                              void* d_out, int out_size)
{
    const float* x  = (const float*)d_in[0];
    const float* Wq = (const float*)d_in[1];
    const float* bq = (const float*)d_in[2];
    const float* Wk = (const float*)d_in[3];
    const float* bk = (const float*)d_in[4];
    const float* Wv = (const float*)d_in[5];
    const float* bv = (const float*)d_in[6];
    float* out = (float*)d_out;

    qkv_kernel<<<dim3(SEQ * BATCH / 64, 3), 256>>>(x, Wq, bq, Wk, bk, Wv, bv);

    const size_t FLASH_SMEM = (size_t)(2 * 64 * 68 + 64 * 64) * sizeof(float); // 51200 B
    cudaFuncSetAttribute(flash_kernel, cudaFuncAttributeMaxDynamicSharedMemorySize,
                         (int)FLASH_SMEM);
    flash_kernel<<<dim3(SEQ / 64, BATCH), 256, FLASH_SMEM>>>(out);
}

// round 2
// speedup vs baseline: 3.7098x; 3.7098x over previous
#include <cuda_runtime.h>
#include <cstdint>

#define EMBED 768
#define HEAD 64
#define SEQ 4096
#define BATCH 4

// Scratch for Q, K, V projections: [B*T, 64] each, fp32
__device__ float g_Q[BATCH * SEQ * HEAD];
__device__ float g_K[BATCH * SEQ * HEAD];
__device__ float g_V[BATCH * SEQ * HEAD];

__device__ __forceinline__ uint32_t f2tf32(float x) {
    uint32_t r;
    asm("cvt.rna.tf32.f32 %0, %1;" : "=r"(r) : "f"(x));
    return r;
}

// D = A(16x8,row) * B(8x8,col) + D, tf32 inputs, f32 accum
__device__ __forceinline__ void mma_tf32(float c[4],
    uint32_t a0, uint32_t a1, uint32_t a2, uint32_t a3,
    uint32_t b0, uint32_t b1)
{
    asm volatile(
        "mma.sync.aligned.m16n8k8.row.col.f32.tf32.tf32.f32 "
        "{%0,%1,%2,%3}, {%4,%5,%6,%7}, {%8,%9}, {%0,%1,%2,%3};"
        : "+f"(c[0]), "+f"(c[1]), "+f"(c[2]), "+f"(c[3])
        : "r"(a0), "r"(a1), "r"(a2), "r"(a3), "r"(b0), "r"(b1));
}

// ---------------------------------------------------------------------------
// QKV projection via tf32 mma. grid(256 row-tiles, 3), 128 threads (4 warps).
// Each block: 64 rows x 64 cols, K=768. Warp w handles rows w*16..w*16+15.
// ---------------------------------------------------------------------------
__global__ __launch_bounds__(128) void qkv_kernel(
    const float* __restrict__ x,
    const float* __restrict__ Wq, const float* __restrict__ bq,
    const float* __restrict__ Wk, const float* __restrict__ bk,
    const float* __restrict__ Wv, const float* __restrict__ bv)
{
    __shared__ uint32_t sx[64 * 68];   // [row][k], tf32
    __shared__ uint32_t sw[64 * 72];   // [k][n],  tf32

    const float* __restrict__ W;
    const float* __restrict__ bias;
    float* out;
    if (blockIdx.y == 0)      { W = Wq; bias = bq; out = g_Q; }
    else if (blockIdx.y == 1) { W = Wk; bias = bk; out = g_K; }
    else                      { W = Wv; bias = bv; out = g_V; }

    const int t    = threadIdx.x;
    const int lane = t & 31;
    const int w16  = (t >> 5) << 4;      // warp * 16
    const int gid  = lane >> 2;
    const int l3   = lane & 3;
    const int row0 = blockIdx.x * 64;

    float o[8][4];
#pragma unroll
    for (int n = 0; n < 8; n++)
#pragma unroll
        for (int c = 0; c < 4; c++) o[n][c] = 0.f;

    for (int e0 = 0; e0 < EMBED; e0 += 64) {
        __syncthreads();
#pragma unroll
        for (int i = 0; i < 8; i++) {
            int fi = t + i * 128;            // 0..1023 float4 slots
            int r  = fi >> 4;
            int c  = (fi & 15) << 2;
            float4 xv = *(const float4*)&x[(size_t)(row0 + r) * EMBED + e0 + c];
            sx[r * 68 + c + 0] = f2tf32(xv.x);
            sx[r * 68 + c + 1] = f2tf32(xv.y);
            sx[r * 68 + c + 2] = f2tf32(xv.z);
            sx[r * 68 + c + 3] = f2tf32(xv.w);
            float4 wv = *(const float4*)&W[(size_t)(e0 + r) * HEAD + c];
            sw[r * 72 + c + 0] = f2tf32(wv.x);
            sw[r * 72 + c + 1] = f2tf32(wv.y);
            sw[r * 72 + c + 2] = f2tf32(wv.z);
            sw[r * 72 + c + 3] = f2tf32(wv.w);
        }
        __syncthreads();

#pragma unroll
        for (int ks = 0; ks < 8; ks++) {
            int h = 8 * ks;
            uint32_t a0 = sx[(w16 + gid) * 68 + h + l3];
            uint32_t a1 = sx[(w16 + gid + 8) * 68 + h + l3];
            uint32_t a2 = sx[(w16 + gid) * 68 + h + l3 + 4];
            uint32_t a3 = sx[(w16 + gid + 8) * 68 + h + l3 + 4];
#pragma unroll
            for (int n = 0; n < 8; n++) {
                uint32_t b0 = sw[(h + l3) * 72 + 8 * n + gid];
                uint32_t b1 = sw[(h + l3 + 4) * 72 + 8 * n + gid];
                mma_tf32(o[n], a0, a1, a2, a3, b0, b1);
            }
        }
    }

#pragma unroll
    for (int n = 0; n < 8; n++) {
        int cbase = 8 * n + 2 * l3;
        float b0 = bias[cbase], b1 = bias[cbase + 1];
        float2 r0 = make_float2(o[n][0] + b0, o[n][1] + b1);
        float2 r1 = make_float2(o[n][2] + b0, o[n][3] + b1);
        *(float2*)&out[(size_t)(row0 + w16 + gid) * HEAD + cbase]     = r0;
        *(float2*)&out[(size_t)(row0 + w16 + gid + 8) * HEAD + cbase] = r1;
    }
}

// ---------------------------------------------------------------------------
// Flash attention, causal, tf32 mma. BM=BN=64, 128 threads (4 warps).
// Warp w owns q rows w*16..w*16+15 of the tile.
// sKP holds K (tf32) during S-compute, then P (tf32) for PV.
// ---------------------------------------------------------------------------
__global__ __launch_bounds__(128) void flash_kernel(float* __restrict__ out)
{
    extern __shared__ uint32_t smem[];
    uint32_t* sQ  = smem;                   // 64 x 68
    uint32_t* sKP = smem + 64 * 68;         // 64 x 68
    uint32_t* sV  = smem + 2 * 64 * 68;     // 64 x 72

    const int b    = blockIdx.y;
    const int qt   = (int)gridDim.x - 1 - (int)blockIdx.x;  // heavy tiles first
    const int t    = threadIdx.x;
    const int lane = t & 31;
    const int w16  = (t >> 5) << 4;
    const int gid  = lane >> 2;
    const int l3   = lane & 3;

    const float* __restrict__ Q = g_Q + (size_t)b * SEQ * HEAD;
    const float* __restrict__ K = g_K + (size_t)b * SEQ * HEAD;
    const float* __restrict__ V = g_V + (size_t)b * SEQ * HEAD;

    // Load + convert Q tile
#pragma unroll
    for (int i = 0; i < 8; i++) {
        int fi = t + i * 128;
        int r  = fi >> 4;
        int c  = (fi & 15) << 2;
        float4 qv = *(const float4*)&Q[(size_t)(qt * 64 + r) * HEAD + c];
        sQ[r * 68 + c + 0] = f2tf32(qv.x);
        sQ[r * 68 + c + 1] = f2tf32(qv.y);
        sQ[r * 68 + c + 2] = f2tf32(qv.z);
        sQ[r * 68 + c + 3] = f2tf32(qv.w);
    }

    float m0 = -1e30f, m1 = -1e30f, l0 = 0.f, l1 = 0.f;
    float o[8][4];
#pragma unroll
    for (int n = 0; n < 8; n++)
#pragma unroll
        for (int c = 0; c < 4; c++) o[n][c] = 0.f;

    const int r0 = w16 + gid;       // local q row (first of the pair)

    for (int kt = 0; kt <= qt; kt++) {
        __syncthreads();   // previous PV reads of sKP/sV done; Q visible on iter 0

        // Load + convert K, V tiles
#pragma unroll
        for (int i = 0; i < 8; i++) {
            int fi = t + i * 128;
            int r  = fi >> 4;
            int c  = (fi & 15) << 2;
            float4 kv = *(const float4*)&K[(size_t)(kt * 64 + r) * HEAD + c];
            sKP[r * 68 + c + 0] = f2tf32(kv.x);
            sKP[r * 68 + c + 1] = f2tf32(kv.y);
            sKP[r * 68 + c + 2] = f2tf32(kv.z);
            sKP[r * 68 + c + 3] = f2tf32(kv.w);
            float4 vv = *(const float4*)&V[(size_t)(kt * 64 + r) * HEAD + c];
            sV[r * 72 + c + 0] = f2tf32(vv.x);
            sV[r * 72 + c + 1] = f2tf32(vv.y);
            sV[r * 72 + c + 2] = f2tf32(vv.z);
            sV[r * 72 + c + 3] = f2tf32(vv.w);
        }
        __syncthreads();

        // S = Q K^T  (per warp: 16 x 64)
        float s[8][4];
#pragma unroll
        for (int n = 0; n < 8; n++)
#pragma unroll
            for (int c = 0; c < 4; c++) s[n][c] = 0.f;

#pragma unroll
        for (int ks = 0; ks < 8; ks++) {
            int h = 8 * ks;
            uint32_t a0 = sQ[(r0) * 68 + h + l3];
            uint32_t a1 = sQ[(r0 + 8) * 68 + h + l3];
            uint32_t a2 = sQ[(r0) * 68 + h + l3 + 4];
            uint32_t a3 = sQ[(r0 + 8) * 68 + h + l3 + 4];
#pragma unroll
            for (int n = 0; n < 8; n++) {
                uint32_t b0 = sKP[(8 * n + gid) * 68 + h + l3];
                uint32_t b1 = sKP[(8 * n + gid) * 68 + h + l3 + 4];
                mma_tf32(s[n], a0, a1, a2, a3, b0, b1);
            }
        }

        // Scale + causal mask (only the diagonal tile)
        const float scale = 0.125f;
        if (kt == qt) {
#pragma unroll
            for (int n = 0; n < 8; n++) {
                int c0 = 8 * n + 2 * l3;
                s[n][0] = (c0     <= r0    ) ? s[n][0] * scale : -1e30f;
                s[n][1] = (c0 + 1 <= r0    ) ? s[n][1] * scale : -1e30f;
                s[n][2] = (c0     <= r0 + 8) ? s[n][2] * scale : -1e30f;
                s[n][3] = (c0 + 1 <= r0 + 8) ? s[n][3] * scale : -1e30f;
            }
        } else {
#pragma unroll
            for (int n = 0; n < 8; n++)
#pragma unroll
                for (int c = 0; c < 4; c++) s[n][c] *= scale;
        }

        // Online softmax. Lanes 4*gid..4*gid+3 share rows r0 / r0+8.
        float mx0 = -1e30f, mx1 = -1e30f;
#pragma unroll
        for (int n = 0; n < 8; n++) {
            mx0 = fmaxf(mx0, fmaxf(s[n][0], s[n][1]));
            mx1 = fmaxf(mx1, fmaxf(s[n][2], s[n][3]));
        }
        mx0 = fmaxf(mx0, __shfl_xor_sync(0xffffffffu, mx0, 1));
        mx0 = fmaxf(mx0, __shfl_xor_sync(0xffffffffu, mx0, 2));
        mx1 = fmaxf(mx1, __shfl_xor_sync(0xffffffffu, mx1, 1));
        mx1 = fmaxf(mx1, __shfl_xor_sync(0xffffffffu, mx1, 2));

        float mn0 = fmaxf(m0, mx0);
        float mn1 = fmaxf(m1, mx1);
        float alpha0 = __expf(m0 - mn0);
        float alpha1 = __expf(m1 - mn1);
        m0 = mn0; m1 = mn1;

        float rs0 = 0.f, rs1 = 0.f;
#pragma unroll
        for (int n = 0; n < 8; n++) {
            s[n][0] = __expf(s[n][0] - mn0);
            s[n][1] = __expf(s[n][1] - mn0);
            s[n][2] = __expf(s[n][2] - mn1);
            s[n][3] = __expf(s[n][3] - mn1);
            rs0 += s[n][0] + s[n][1];
            rs1 += s[n][2] + s[n][3];
        }
        rs0 += __shfl_xor_sync(0xffffffffu, rs0, 1);
        rs0 += __shfl_xor_sync(0xffffffffu, rs0, 2);
        rs1 += __shfl_xor_sync(0xffffffffu, rs1, 1);
        rs1 += __shfl_xor_sync(0xffffffffu, rs1, 2);
        l0 = l0 * alpha0 + rs0;
        l1 = l1 * alpha1 + rs1;

#pragma unroll
        for (int n = 0; n < 8; n++) {
            o[n][0] *= alpha0; o[n][1] *= alpha0;
            o[n][2] *= alpha1; o[n][3] *= alpha1;
        }

        __syncthreads();   // all warps done reading K before P overwrites it

        // Write P (tf32) into sKP, C-layout -> row-major
#pragma unroll
        for (int n = 0; n < 8; n++) {
            int cbase = 8 * n + 2 * l3;
            sKP[(r0) * 68 + cbase + 0]     = f2tf32(s[n][0]);
            sKP[(r0) * 68 + cbase + 1]     = f2tf32(s[n][1]);
            sKP[(r0 + 8) * 68 + cbase + 0] = f2tf32(s[n][2]);
            sKP[(r0 + 8) * 68 + cbase + 1] = f2tf32(s[n][3]);
        }
        __syncthreads();

        // O += P @ V
#pragma unroll
        for (int ks = 0; ks < 8; ks++) {
            int k0 = 8 * ks;
            uint32_t a0 = sKP[(r0) * 68 + k0 + l3];
            uint32_t a1 = sKP[(r0 + 8) * 68 + k0 + l3];
            uint32_t a2 = sKP[(r0) * 68 + k0 + l3 + 4];
            uint32_t a3 = sKP[(r0 + 8) * 68 + k0 + l3 + 4];
#pragma unroll
            for (int n = 0; n < 8; n++) {
                uint32_t b0 = sV[(k0 + l3) * 72 + 8 * n + gid];
                uint32_t b1 = sV[(k0 + l3 + 4) * 72 + 8 * n + gid];
                mma_tf32(o[n], a0, a1, a2, a3, b0, b1);
            }
        }
    }

    // Normalize + write out [B, T, H]
    float inv0 = 1.f / l0;
    float inv1 = 1.f / l1;
    size_t orow0 = (size_t)b * SEQ + qt * 64 + r0;
#pragma unroll
    for (int n = 0; n < 8; n++) {
        int cbase = 8 * n + 2 * l3;
        float2 v0 = make_float2(o[n][0] * inv0, o[n][1] * inv0);
        float2 v1 = make_float2(o[n][2] * inv1, o[n][3] * inv1);
        *(float2*)&out[orow0 * HEAD + cbase]       = v0;
        *(float2*)&out[(orow0 + 8) * HEAD + cbase] = v1;
    }
}

extern "C" void kernel_launch(void* const* d_in, const int* in_sizes, int n_in,
                              void* d_out, int out_size)
{
    const float* x  = (const float*)d_in[0];
    const float* Wq = (const float*)d_in[1];
    const float* bq = (const float*)d_in[2];
    const float* Wk = (const float*)d_in[3];
    const float* bk = (const float*)d_in[4];
    const float* Wv = (const float*)d_in[5];
    const float* bv = (const float*)d_in[6];
    float* out = (float*)d_out;

    qkv_kernel<<<dim3(SEQ * BATCH / 64, 3), 128>>>(x, Wq, bq, Wk, bk, Wv, bv);

    const size_t FLASH_SMEM = (size_t)(2 * 64 * 68 + 64 * 72) * sizeof(uint32_t); // 53248
    cudaFuncSetAttribute(flash_kernel, cudaFuncAttributeMaxDynamicSharedMemorySize,
                         (int)FLASH_SMEM);
    flash_kernel<<<dim3(SEQ / 64, BATCH), 128, FLASH_SMEM>>>(out);
}

// round 3
// speedup vs baseline: 4.3321x; 1.1677x over previous
#include <cuda_runtime.h>
#include <cstdint>

#define EMBED 768
#define HEAD 64
#define SEQ 4096
#define BATCH 4

// Scratch for Q, K, V projections: [B*T, 64] each, fp32
__device__ float g_Q[BATCH * SEQ * HEAD];
__device__ float g_K[BATCH * SEQ * HEAD];
__device__ float g_V[BATCH * SEQ * HEAD];

__device__ __forceinline__ uint32_t f2tf32(float x) {
    uint32_t r;
    asm("cvt.rna.tf32.f32 %0, %1;" : "=r"(r) : "f"(x));
    return r;
}

// D = A(16x8,row) * B(8x8,col) + D, tf32 inputs, f32 accum
__device__ __forceinline__ void mma_tf32(float c[4],
    uint32_t a0, uint32_t a1, uint32_t a2, uint32_t a3,
    uint32_t b0, uint32_t b1)
{
    asm volatile(
        "mma.sync.aligned.m16n8k8.row.col.f32.tf32.tf32.f32 "
        "{%0,%1,%2,%3}, {%4,%5,%6,%7}, {%8,%9}, {%0,%1,%2,%3};"
        : "+f"(c[0]), "+f"(c[1]), "+f"(c[2]), "+f"(c[3])
        : "r"(a0), "r"(a1), "r"(a2), "r"(a3), "r"(b0), "r"(b1));
}

#define GBAR(id) asm volatile("bar.sync %0, %1;" :: "r"(id), "r"(128) : "memory")

// ---------------------------------------------------------------------------
// QKV projection via tf32 mma. BM=128, 256 threads (8 warps), grid (128, 3).
// Warp w handles rows w*16..w*16+15 of the 128-row tile.
// ---------------------------------------------------------------------------
__global__ __launch_bounds__(256, 2) void qkv_kernel(
    const float* __restrict__ x,
    const float* __restrict__ Wq, const float* __restrict__ bq,
    const float* __restrict__ Wk, const float* __restrict__ bk,
    const float* __restrict__ Wv, const float* __restrict__ bv)
{
    extern __shared__ uint32_t dsm[];
    uint32_t* sx = dsm;                 // 128 x 68
    uint32_t* sw = dsm + 128 * 68;      // 64 x 72

    const float* __restrict__ W;
    const float* __restrict__ bias;
    float* out;
    if (blockIdx.y == 0)      { W = Wq; bias = bq; out = g_Q; }
    else if (blockIdx.y == 1) { W = Wk; bias = bk; out = g_K; }
    else                      { W = Wv; bias = bv; out = g_V; }

    const int t    = threadIdx.x;
    const int lane = t & 31;
    const int w16  = (t >> 5) << 4;      // warp * 16
    const int gid  = lane >> 2;
    const int l3   = lane & 3;
    const int row0 = blockIdx.x * 128;

    float o[8][4];
#pragma unroll
    for (int n = 0; n < 8; n++)
#pragma unroll
        for (int c = 0; c < 4; c++) o[n][c] = 0.f;

    for (int e0 = 0; e0 < EMBED; e0 += 64) {
        __syncthreads();
#pragma unroll
        for (int i = 0; i < 8; i++) {
            int fi = t + i * 256;            // 0..2047 float4 slots of sx
            int r  = fi >> 4;
            int c  = (fi & 15) << 2;
            float4 xv = *(const float4*)&x[(size_t)(row0 + r) * EMBED + e0 + c];
            sx[r * 68 + c + 0] = f2tf32(xv.x);
            sx[r * 68 + c + 1] = f2tf32(xv.y);
            sx[r * 68 + c + 2] = f2tf32(xv.z);
            sx[r * 68 + c + 3] = f2tf32(xv.w);
        }
#pragma unroll
        for (int i = 0; i < 4; i++) {
            int fi = t + i * 256;            // 0..1023 float4 slots of sw
            int r  = fi >> 4;
            int c  = (fi & 15) << 2;
            float4 wv = *(const float4*)&W[(size_t)(e0 + r) * HEAD + c];
            sw[r * 72 + c + 0] = f2tf32(wv.x);
            sw[r * 72 + c + 1] = f2tf32(wv.y);
            sw[r * 72 + c + 2] = f2tf32(wv.z);
            sw[r * 72 + c + 3] = f2tf32(wv.w);
        }
        __syncthreads();

#pragma unroll
        for (int ks = 0; ks < 8; ks++) {
            int h = 8 * ks;
            uint32_t a0 = sx[(w16 + gid) * 68 + h + l3];
            uint32_t a1 = sx[(w16 + gid + 8) * 68 + h + l3];
            uint32_t a2 = sx[(w16 + gid) * 68 + h + l3 + 4];
            uint32_t a3 = sx[(w16 + gid + 8) * 68 + h + l3 + 4];
#pragma unroll
            for (int n = 0; n < 8; n++) {
                uint32_t b0 = sw[(h + l3) * 72 + 8 * n + gid];
                uint32_t b1 = sw[(h + l3 + 4) * 72 + 8 * n + gid];
                mma_tf32(o[n], a0, a1, a2, a3, b0, b1);
            }
        }
    }

#pragma unroll
    for (int n = 0; n < 8; n++) {
        int cbase = 8 * n + 2 * l3;
        float b0 = bias[cbase], b1 = bias[cbase + 1];
        float2 r0v = make_float2(o[n][0] + b0, o[n][1] + b1);
        float2 r1v = make_float2(o[n][2] + b0, o[n][3] + b1);
        *(float2*)&out[(size_t)(row0 + w16 + gid) * HEAD + cbase]     = r0v;
        *(float2*)&out[(size_t)(row0 + w16 + gid + 8) * HEAD + cbase] = r1v;
    }
}

// ---------------------------------------------------------------------------
// Flash attention, causal, tf32 mma, split-kt across 2 warp-groups.
// BM=64, 256 threads. Group g (warps 4g..4g+3) handles kt = g, g+2, ...
// with private (m,l,O) state and private K/V smem buffers; groups merge once
// at the end. Group-local sync via named barriers (bar.sync g+1, 128).
// ---------------------------------------------------------------------------
__global__ __launch_bounds__(256, 2) void flash_kernel(float* __restrict__ out)
{
    extern __shared__ uint32_t smem[];
    uint32_t* sQ = smem;                           // 64 x 68 (shared, read-only)
    // per-group buffers
    // group g: sK at smem + 64*68 + g*64*68 ; sV at smem + 3*64*68 + g*64*72
    const int b    = blockIdx.y;
    const int qt   = (int)gridDim.x - 1 - (int)blockIdx.x;  // heavy tiles first
    const int t    = threadIdx.x;
    const int lane = t & 31;
    const int warp = t >> 5;
    const int g    = warp >> 2;          // warp-group 0/1
    const int tg   = t & 127;            // thread id within group
    const int w16  = (warp & 3) << 4;
    const int gid  = lane >> 2;
    const int l3   = lane & 3;
    const int r0   = w16 + gid;          // local q row (first of pair)

    uint32_t* sK = smem + 64 * 68 + g * 64 * 68;
    uint32_t* sV = smem + 3 * 64 * 68 + g * 64 * 72;

    const float* __restrict__ Q = g_Q + (size_t)b * SEQ * HEAD;
    const float* __restrict__ K = g_K + (size_t)b * SEQ * HEAD;
    const float* __restrict__ V = g_V + (size_t)b * SEQ * HEAD;

    // Load + convert Q tile (all 256 threads)
#pragma unroll
    for (int i = 0; i < 4; i++) {
        int fi = t + i * 256;
        int r  = fi >> 4;
        int c  = (fi & 15) << 2;
        float4 qv = *(const float4*)&Q[(size_t)(qt * 64 + r) * HEAD + c];
        sQ[r * 68 + c + 0] = f2tf32(qv.x);
        sQ[r * 68 + c + 1] = f2tf32(qv.y);
        sQ[r * 68 + c + 2] = f2tf32(qv.z);
        sQ[r * 68 + c + 3] = f2tf32(qv.w);
    }
    __syncthreads();

    float m0 = -1e30f, m1 = -1e30f, l0 = 0.f, l1 = 0.f;
    float o[8][4];
#pragma unroll
    for (int n = 0; n < 8; n++)
#pragma unroll
        for (int c = 0; c < 4; c++) o[n][c] = 0.f;

    for (int kt = g; kt <= qt; kt += 2) {
        GBAR(g + 1);   // group's previous PV reads of sK/sV done

        // Load + convert this group's K, V tiles (128 threads)
#pragma unroll
        for (int i = 0; i < 8; i++) {
            int fi = tg + i * 128;
            int r  = fi >> 4;
            int c  = (fi & 15) << 2;
            float4 kv = *(const float4*)&K[(size_t)(kt * 64 + r) * HEAD + c];
            sK[r * 68 + c + 0] = f2tf32(kv.x);
            sK[r * 68 + c + 1] = f2tf32(kv.y);
            sK[r * 68 + c + 2] = f2tf32(kv.z);
            sK[r * 68 + c + 3] = f2tf32(kv.w);
            float4 vv = *(const float4*)&V[(size_t)(kt * 64 + r) * HEAD + c];
            sV[r * 72 + c + 0] = f2tf32(vv.x);
            sV[r * 72 + c + 1] = f2tf32(vv.y);
            sV[r * 72 + c + 2] = f2tf32(vv.z);
            sV[r * 72 + c + 3] = f2tf32(vv.w);
        }
        GBAR(g + 1);

        // S = Q K^T  (per warp: 16 x 64)
        float s[8][4];
#pragma unroll
        for (int n = 0; n < 8; n++)
#pragma unroll
            for (int c = 0; c < 4; c++) s[n][c] = 0.f;

#pragma unroll
        for (int ks = 0; ks < 8; ks++) {
            int h = 8 * ks;
            uint32_t a0 = sQ[(r0) * 68 + h + l3];
            uint32_t a1 = sQ[(r0 + 8) * 68 + h + l3];
            uint32_t a2 = sQ[(r0) * 68 + h + l3 + 4];
            uint32_t a3 = sQ[(r0 + 8) * 68 + h + l3 + 4];
#pragma unroll
            for (int n = 0; n < 8; n++) {
                uint32_t b0 = sK[(8 * n + gid) * 68 + h + l3];
                uint32_t b1 = sK[(8 * n + gid) * 68 + h + l3 + 4];
                mma_tf32(s[n], a0, a1, a2, a3, b0, b1);
            }
        }

        // Scale + causal mask (diagonal tile only)
        const float scale = 0.125f;
        if (kt == qt) {
#pragma unroll
            for (int n = 0; n < 8; n++) {
                int c0 = 8 * n + 2 * l3;
                s[n][0] = (c0     <= r0    ) ? s[n][0] * scale : -1e30f;
                s[n][1] = (c0 + 1 <= r0    ) ? s[n][1] * scale : -1e30f;
                s[n][2] = (c0     <= r0 + 8) ? s[n][2] * scale : -1e30f;
                s[n][3] = (c0 + 1 <= r0 + 8) ? s[n][3] * scale : -1e30f;
            }
        } else {
#pragma unroll
            for (int n = 0; n < 8; n++)
#pragma unroll
                for (int c = 0; c < 4; c++) s[n][c] *= scale;
        }

        // Online softmax (rows r0 / r0+8; 4 lanes per row)
        float mx0 = -1e30f, mx1 = -1e30f;
#pragma unroll
        for (int n = 0; n < 8; n++) {
            mx0 = fmaxf(mx0, fmaxf(s[n][0], s[n][1]));
            mx1 = fmaxf(mx1, fmaxf(s[n][2], s[n][3]));
        }
        mx0 = fmaxf(mx0, __shfl_xor_sync(0xffffffffu, mx0, 1));
        mx0 = fmaxf(mx0, __shfl_xor_sync(0xffffffffu, mx0, 2));
        mx1 = fmaxf(mx1, __shfl_xor_sync(0xffffffffu, mx1, 1));
        mx1 = fmaxf(mx1, __shfl_xor_sync(0xffffffffu, mx1, 2));

        float mn0 = fmaxf(m0, mx0);
        float mn1 = fmaxf(m1, mx1);
        float alpha0 = __expf(m0 - mn0);
        float alpha1 = __expf(m1 - mn1);
        m0 = mn0; m1 = mn1;

        float rs0 = 0.f, rs1 = 0.f;
#pragma unroll
        for (int n = 0; n < 8; n++) {
            s[n][0] = __expf(s[n][0] - mn0);
            s[n][1] = __expf(s[n][1] - mn0);
            s[n][2] = __expf(s[n][2] - mn1);
            s[n][3] = __expf(s[n][3] - mn1);
            rs0 += s[n][0] + s[n][1];
            rs1 += s[n][2] + s[n][3];
        }
        rs0 += __shfl_xor_sync(0xffffffffu, rs0, 1);
        rs0 += __shfl_xor_sync(0xffffffffu, rs0, 2);
        rs1 += __shfl_xor_sync(0xffffffffu, rs1, 1);
        rs1 += __shfl_xor_sync(0xffffffffu, rs1, 2);
        l0 = l0 * alpha0 + rs0;
        l1 = l1 * alpha1 + rs1;

#pragma unroll
        for (int n = 0; n < 8; n++) {
            o[n][0] *= alpha0; o[n][1] *= alpha0;
            o[n][2] *= alpha1; o[n][3] *= alpha1;
        }

        GBAR(g + 1);   // group warps done reading sK before P overwrites it

        // Write P (tf32) into sK
#pragma unroll
        for (int n = 0; n < 8; n++) {
            int cbase = 8 * n + 2 * l3;
            sK[(r0) * 68 + cbase + 0]     = f2tf32(s[n][0]);
            sK[(r0) * 68 + cbase + 1]     = f2tf32(s[n][1]);
            sK[(r0 + 8) * 68 + cbase + 0] = f2tf32(s[n][2]);
            sK[(r0 + 8) * 68 + cbase + 1] = f2tf32(s[n][3]);
        }
        GBAR(g + 1);

        // O += P @ V
#pragma unroll
        for (int ks = 0; ks < 8; ks++) {
            int k0 = 8 * ks;
            uint32_t a0 = sK[(r0) * 68 + k0 + l3];
            uint32_t a1 = sK[(r0 + 8) * 68 + k0 + l3];
            uint32_t a2 = sK[(r0) * 68 + k0 + l3 + 4];
            uint32_t a3 = sK[(r0 + 8) * 68 + k0 + l3 + 4];
#pragma unroll
            for (int n = 0; n < 8; n++) {
                uint32_t b0 = sV[(k0 + l3) * 72 + 8 * n + gid];
                uint32_t b1 = sV[(k0 + l3 + 4) * 72 + 8 * n + gid];
                mma_tf32(o[n], a0, a1, a2, a3, b0, b1);
            }
        }
    }

    // ---- Merge the two groups' partial (m, l, O) ----
    __syncthreads();                    // both groups done; sQ free for reuse
    float* sML = (float*)smem;          // [2][64][2] floats
    if (l3 == 0) {
        sML[((g * 64 + r0)     << 1) + 0] = m0;
        sML[((g * 64 + r0)     << 1) + 1] = l0;
        sML[((g * 64 + r0 + 8) << 1) + 0] = m1;
        sML[((g * 64 + r0 + 8) << 1) + 1] = l1;
    }
    __syncthreads();
    const int og = 1 - g;
    float mo0 = sML[((og * 64 + r0)     << 1) + 0];
    float lo0 = sML[((og * 64 + r0)     << 1) + 1];
    float mo1 = sML[((og * 64 + r0 + 8) << 1) + 0];
    float lo1 = sML[((og * 64 + r0 + 8) << 1) + 1];

    float M0 = fmaxf(m0, mo0), M1 = fmaxf(m1, mo1);
    float sc0 = __expf(m0 - M0), sc1 = __expf(m1 - M1);
    float L0 = l0 * sc0 + lo0 * __expf(mo0 - M0);
    float L1 = l1 * sc1 + lo1 * __expf(mo1 - M1);

#pragma unroll
    for (int n = 0; n < 8; n++) {
        o[n][0] *= sc0; o[n][1] *= sc0;
        o[n][2] *= sc1; o[n][3] *= sc1;
    }

    float* sOB = (float*)(smem + 64 * 68);   // 64 x 68 float buffer
    if (g == 1) {
#pragma unroll
        for (int n = 0; n < 8; n++) {
            int cbase = 8 * n + 2 * l3;
            sOB[(r0) * 68 + cbase + 0]     = o[n][0];
            sOB[(r0) * 68 + cbase + 1]     = o[n][1];
            sOB[(r0 + 8) * 68 + cbase + 0] = o[n][2];
            sOB[(r0 + 8) * 68 + cbase + 1] = o[n][3];
        }
    }
    __syncthreads();
    if (g == 0) {
        float inv0 = 1.f / L0;
        float inv1 = 1.f / L1;
        size_t orow0 = (size_t)b * SEQ + qt * 64 + r0;
#pragma unroll
        for (int n = 0; n < 8; n++) {
            int cbase = 8 * n + 2 * l3;
            float2 v0, v1;
            v0.x = (o[n][0] + sOB[(r0) * 68 + cbase + 0])     * inv0;
            v0.y = (o[n][1] + sOB[(r0) * 68 + cbase + 1])     * inv0;
            v1.x = (o[n][2] + sOB[(r0 + 8) * 68 + cbase + 0]) * inv1;
            v1.y = (o[n][3] + sOB[(r0 + 8) * 68 + cbase + 1]) * inv1;
            *(float2*)&out[orow0 * HEAD + cbase]       = v0;
            *(float2*)&out[(orow0 + 8) * HEAD + cbase] = v1;
        }
    }
}

extern "C" void kernel_launch(void* const* d_in, const int* in_sizes, int n_in,
                              void* d_out, int out_size)
{
    const float* x  = (const float*)d_in[0];
    const float* Wq = (const float*)d_in[1];
    const float* bq = (const float*)d_in[2];
    const float* Wk = (const float*)d_in[3];
    const float* bk = (const float*)d_in[4];
    const float* Wv = (const float*)d_in[5];
    const float* bv = (const float*)d_in[6];
    float* out = (float*)d_out;

    const size_t QKV_SMEM = (size_t)(128 * 68 + 64 * 72) * sizeof(uint32_t);   // 53248
    cudaFuncSetAttribute(qkv_kernel, cudaFuncAttributeMaxDynamicSharedMemorySize,
                         (int)QKV_SMEM);
    qkv_kernel<<<dim3(SEQ * BATCH / 128, 3), 256, QKV_SMEM>>>(x, Wq, bq, Wk, bk, Wv, bv);

    // sQ(64*68) + 2*sK(64*68) + 2*sV(64*72) words
    const size_t FLASH_SMEM = (size_t)(3 * 64 * 68 + 2 * 64 * 72) * sizeof(uint32_t); // 89088
    cudaFuncSetAttribute(flash_kernel, cudaFuncAttributeMaxDynamicSharedMemorySize,
                         (int)FLASH_SMEM);
    flash_kernel<<<dim3(SEQ / 64, BATCH), 256, FLASH_SMEM>>>(out);
}